// round 16
// baseline (speedup 1.0000x reference)
#include <cuda_runtime.h>
#include <cuda_bf16.h>
#include <cuda_fp16.h>
#include <math.h>
#include <cstdint>

// Problem constants (LocalAttention: B=4, T=2048, C=1024, WIN=16)
#define BB   4
#define TT   2048
#define CC   1024
#define HALF 8
#define WW   17
#define MM   8192

// GEMM tiling: CTA tile 128x64, warp tile 32x32, 8 warps (4M x 2N)
// BK=64 per stage (two 32-wide sub-tiles), 3 stages, 3 CTAs/SM.
#define BM 128
#define BN 64
#define BKK 64                    // fp16 K elems per stage
#define NIT (CC / BKK)            // 16 k-iterations
#define ATILE_B 8192              // 128 rows x 32 f16 x 2B (one sub-tile)
#define BTILE_B 4096              // 64 rows x 32 f16 x 2B  (one sub-tile)
#define QSTAGE_B (2 * ATILE_B + 2 * BTILE_B)  // 24576
#define NSTAGE 3
#define GEMM_SMEM (NSTAGE * QSTAGE_B)         // 73728
#define GRID_PERSIST 444          // 3 CTAs per SM

// Attention: block = 8 t-positions, C chunked into 4x256, double buffer
#define GG   8
#define CHW  256
#define NCH  4
#define WROWS 24
#define ATTN_SMEM (2 * WROWS * CHW * 4)   // 49152

// ---------------------------------------------------------------------------
// Scratch (device globals: allocation-free rule)
// ---------------------------------------------------------------------------
__device__ float g_q[MM * CC];
__device__ float g_k[MM * CC];
__device__ float g_v[MM * CC];
__device__ __half g_x16[MM * CC];
__device__ __half g_c16[MM * CC];
__device__ __half g_w16[4 * CC * CC];   // Wq, Wk, Wv, Wo (single fp16)

// ---------------------------------------------------------------------------
// PTX helpers (sm_80+ base-target instructions only)
// ---------------------------------------------------------------------------
__device__ __forceinline__ uint32_t smem_u32(const void* p) {
    uint32_t a;
    asm("{ .reg .u64 t; cvta.to.shared.u64 t, %1; cvt.u32.u64 %0, t; }" : "=r"(a) : "l"(p));
    return a;
}
__device__ __forceinline__ void cp_async16(uint32_t dst, const void* src) {
    asm volatile("cp.async.cg.shared.global [%0], [%1], 16;" :: "r"(dst), "l"(src));
}
__device__ __forceinline__ void cp_commit() { asm volatile("cp.async.commit_group;"); }
template <int N>
__device__ __forceinline__ void cp_wait() { asm volatile("cp.async.wait_group %0;" :: "n"(N)); }

__device__ __forceinline__ void ldsm_x4(uint32_t& r0, uint32_t& r1, uint32_t& r2, uint32_t& r3,
                                        uint32_t addr) {
    asm volatile("ldmatrix.sync.aligned.m8n8.x4.shared.b16 {%0,%1,%2,%3}, [%4];"
                 : "=r"(r0), "=r"(r1), "=r"(r2), "=r"(r3) : "r"(addr));
}
__device__ __forceinline__ void mma_f16(float* d, const uint32_t* a, uint32_t b0, uint32_t b1) {
    asm volatile(
        "mma.sync.aligned.m16n8k16.row.col.f32.f16.f16.f32 "
        "{%0,%1,%2,%3}, {%4,%5,%6,%7}, {%8,%9}, {%0,%1,%2,%3};"
        : "+f"(d[0]), "+f"(d[1]), "+f"(d[2]), "+f"(d[3])
        : "r"(a[0]), "r"(a[1]), "r"(a[2]), "r"(a[3]), "r"(b0), "r"(b1));
}

// Swizzle on 64B logical rows (conflict-free ldmatrix + STS16)
#define SWZ(off) ((off) ^ (((off) >> 3) & 0x70))

__device__ __forceinline__ uint32_t ldsm_addr(uint32_t tile_base, int row0, int chunk0, int lane) {
    int row   = row0 + (lane & 15);
    int chunk = chunk0 + (lane >> 4);
    uint32_t off = (uint32_t)row * 64 + (uint32_t)chunk * 16;
    return tile_base + SWZ(off);
}

// ---------------------------------------------------------------------------
// fp32 -> single fp16; blockIdx.y selects among up to 4 sources.
// ---------------------------------------------------------------------------
__global__ __launch_bounds__(256)
void conv_f16(const float* __restrict__ s0, const float* __restrict__ s1,
              const float* __restrict__ s2, const float* __restrict__ s3,
              __half* __restrict__ out, int n4)
{
    const int w = blockIdx.y;
    const float* srcs[4] = {s0, s1, s2, s3};
    int i = blockIdx.x * blockDim.x + threadIdx.x;
    if (i >= n4) return;
    float4 v = ((const float4*)srcs[w])[i];
    __half h[4] = {__float2half(v.x), __float2half(v.y), __float2half(v.z), __float2half(v.w)};
    ((ushort4*)out)[(size_t)w * n4 + i] =
        make_ushort4(*(unsigned short*)&h[0], *(unsigned short*)&h[1],
                     *(unsigned short*)&h[2], *(unsigned short*)&h[3]);
}

// ---------------------------------------------------------------------------
// Persistent fp16 NT GEMM, 128x64 CTA tile, BK=64, 3 stages, 3 CTAs/SM.
// out[m,n] = sum_k A[m,k]*W[n,k] + bias[n]
// nblk = weight 64-col blocks (48 fused QKV, 16 Wo); which = nb>>4.
// ---------------------------------------------------------------------------
__global__ __launch_bounds__(256, 3)
void gemm_f16(const __half* __restrict__ Ah, const __half* __restrict__ Wh,
              const float* __restrict__ b0, const float* __restrict__ b1,
              const float* __restrict__ b2,
              float* __restrict__ o0, float* __restrict__ o1, float* __restrict__ o2,
              int ntiles, int nblk)
{
    extern __shared__ char sm[];
    const uint32_t sbase = smem_u32(sm);
    const int tid   = threadIdx.x;
    const int lane  = tid & 31;
    const int warp  = tid >> 5;
    const int warpM = warp >> 1;
    const int warpN = warp & 1;

    const int larow = tid >> 1;
    const int lac0  = (tid & 1) * 2;
    uint32_t daphys[2];
#pragma unroll
    for (int i = 0; i < 2; i++) {
        uint32_t off = (uint32_t)larow * 64 + (uint32_t)(lac0 + i) * 16;
        daphys[i] = SWZ(off);
    }
    const int lbrow = tid >> 2;
    const int lbc   = tid & 3;
    const uint32_t dbphys = SWZ((uint32_t)lbrow * 64 + (uint32_t)lbc * 16);

    for (int tile = blockIdx.x; tile < ntiles; tile += gridDim.x) {
        const int mb = tile / nblk;
        const int nb = tile - mb * nblk;
        const int bm = mb * BM;
        const int which = nb >> 4;
        const int col0  = (nb & 15) * BN;
        const float* bias = (which == 0) ? b0 : ((which == 1) ? b1 : b2);
        float* Cout       = (which == 0) ? o0 : ((which == 1) ? o1 : o2);

        const __half* gA = Ah + (size_t)(bm + larow) * CC;
        const __half* gW = Wh + (size_t)(nb * BN + lbrow) * CC;

// One stage = K range [kc, kc+64): two 32-wide sub-tiles for A and for W.
#define ISSUE_STAGE(s, kc) do { \
    uint32_t stg_ = sbase + (uint32_t)(s) * QSTAGE_B; \
    _Pragma("unroll") \
    for (int sub_ = 0; sub_ < 2; sub_++) { \
        _Pragma("unroll") \
        for (int i_ = 0; i_ < 2; i_++) { \
            cp_async16(stg_ + sub_ * ATILE_B + daphys[i_], \
                       gA + (kc) + sub_ * 32 + (lac0 + i_) * 8); \
        } \
        cp_async16(stg_ + 2 * ATILE_B + sub_ * BTILE_B + dbphys, \
                   gW + (kc) + sub_ * 32 + lbc * 8); \
    } \
    cp_commit(); \
} while (0)

        float acc[2][4][4];
#pragma unroll
        for (int mt = 0; mt < 2; mt++)
#pragma unroll
            for (int nt = 0; nt < 4; nt++)
#pragma unroll
                for (int r = 0; r < 4; r++) acc[mt][nt][r] = 0.f;

        // 3-stage pipeline: prefetch stages 0,1; steady state keeps 2 in flight.
        ISSUE_STAGE(0, 0);
        ISSUE_STAGE(1, 64);

        for (int it = 0; it < NIT; it++) {
            cp_wait<1>();
            __syncthreads();
            // Overwrites buffer (it+2)%3 == (it-1)%3, whose readers finished
            // before the sync above.
            if (it + 2 < NIT) { ISSUE_STAGE((it + 2) % NSTAGE, (it + 2) * BKK); }
            else              { cp_commit(); }

            const uint32_t stg = sbase + (uint32_t)(it % NSTAGE) * QSTAGE_B;
#pragma unroll
            for (int g = 0; g < 4; g++) {        // four k16 steps per stage
                const int tsel = g >> 1;         // sub-tile
                const int ch0  = (g & 1) * 2;    // 16B-chunk within sub-tile
                uint32_t afr[2][4];              // [mt][reg]
#pragma unroll
                for (int mt = 0; mt < 2; mt++) {
                    uint32_t ad = ldsm_addr(stg + tsel * ATILE_B,
                                            warpM * 32 + mt * 16, ch0, lane);
                    ldsm_x4(afr[mt][0], afr[mt][1], afr[mt][2], afr[mt][3], ad);
                }
                uint32_t bfr[2][4];              // [gp][reg]
#pragma unroll
                for (int gp = 0; gp < 2; gp++) {
                    uint32_t ad = ldsm_addr(stg + 2 * ATILE_B + tsel * BTILE_B,
                                            warpN * 32 + gp * 16, ch0, lane);
                    ldsm_x4(bfr[gp][0], bfr[gp][1], bfr[gp][2], bfr[gp][3], ad);
                }
#pragma unroll
                for (int mt = 0; mt < 2; mt++)
#pragma unroll
                    for (int gp = 0; gp < 2; gp++) {
                        mma_f16(acc[mt][gp * 2 + 0], afr[mt], bfr[gp][0], bfr[gp][2]);
                        mma_f16(acc[mt][gp * 2 + 1], afr[mt], bfr[gp][1], bfr[gp][3]);
                    }
            }
        }

        // Tile-boundary barrier: the it=NIT-1 consumption of stage (NIT-1)%3
        // above is unsynced; the NEXT tile's prologue writes stages 0 and 1.
        // With NSTAGE=3 those sets overlap (stage 0), so all warps must finish
        // reading before any warp issues the next tile's loads. (R15 bug.)
        __syncthreads();

#pragma unroll
        for (int mt = 0; mt < 2; mt++) {
            const int row0 = bm + warpM * 32 + mt * 16 + (lane >> 2);
#pragma unroll
            for (int nt = 0; nt < 4; nt++) {
                const int col = col0 + warpN * 32 + nt * 8 + (lane & 3) * 2;
                const float c0 = bias[col], c1 = bias[col + 1];
                float2 v0 = make_float2(acc[mt][nt][0] + c0, acc[mt][nt][1] + c1);
                float2 v1 = make_float2(acc[mt][nt][2] + c0, acc[mt][nt][3] + c1);
                *(float2*)(Cout + (size_t)row0 * CC + col)       = v0;
                *(float2*)(Cout + (size_t)(row0 + 8) * CC + col) = v1;
            }
        }
#undef ISSUE_STAGE
    }
}

// ---------------------------------------------------------------------------
// Chunked smem local attention: block = 8 t (1 warp each), C in 4x256 chunks,
// 2x24KB double-buffered window via cp.async. Writes ctx as single fp16.
// ---------------------------------------------------------------------------
__device__ __forceinline__ void store_h(__half* ch, size_t off, float4 a) {
    float f[4] = {a.x, a.y, a.z, a.w};
    unsigned short h[4];
#pragma unroll
    for (int c = 0; c < 4; c++) {
        __half hb = __float2half(f[c]);
        h[c] = *(unsigned short*)&hb;
    }
    *(ushort4*)(ch + off) = make_ushort4(h[0], h[1], h[2], h[3]);
}

#define ATTN_ISSUE(dstu32, srcp, c) do { \
    _Pragma("unroll") \
    for (int i_ = 0; i_ < 6; i_++) { \
        int idx_ = i_ * 256 + tid; \
        int r_ = idx_ >> 6, f4_ = idx_ & 63; \
        int trow_ = t0 - HALF + r_; \
        if (trow_ >= 0 && trow_ < TT) \
            cp_async16((dstu32) + ((uint32_t)r_ * CHW + f4_ * 4) * 4, \
                       (srcp) + base + (size_t)trow_ * CC + (c) * CHW + f4_ * 4); \
    } \
    cp_commit(); \
} while (0)

__global__ __launch_bounds__(256)
void local_attn(const float* __restrict__ q, const float* __restrict__ k,
                const float* __restrict__ v, __half* __restrict__ ch)
{
    extern __shared__ float sh[];
    float* bufp[2] = { sh, sh + WROWS * CHW };
    __shared__ float swgt[GG][WW];

    const int b    = blockIdx.y;
    const int t0   = blockIdx.x * GG;
    const int tid  = threadIdx.x;
    const int warp = tid >> 5;
    const int lane = tid & 31;
    const uint32_t sb[2] = { smem_u32(bufp[0]), smem_u32(bufp[1]) };
    const size_t base = (size_t)b * TT * CC;

    const int t = t0 + warp;
    const size_t btrow = base + (size_t)t * CC;

    float p[WW];
#pragma unroll
    for (int w = 0; w < WW; w++) p[w] = 0.f;

    // ---- Score pass over K chunks ----
    ATTN_ISSUE(sb[0], k, 0);
    for (int c = 0; c < NCH; c++) {
        cp_wait<0>();
        __syncthreads();
        if (c + 1 < NCH) ATTN_ISSUE(sb[(c + 1) & 1], k, c + 1);
        const float4* kb = (const float4*)bufp[c & 1];
        const float4* qr = (const float4*)(q + btrow);
        float4 q0 = qr[c * 64 + lane];
        float4 q1 = qr[c * 64 + lane + 32];
#pragma unroll
        for (int w = 0; w < WW; w++) {
            int tt = t + w - HALF;
            if (tt < 0 || tt >= TT) continue;
            float4 k0 = kb[(warp + w) * 64 + lane];
            float4 k1 = kb[(warp + w) * 64 + lane + 32];
            p[w] += q0.x * k0.x + q0.y * k0.y + q0.z * k0.z + q0.w * k0.w
                  + q1.x * k1.x + q1.y * k1.y + q1.z * k1.z + q1.w * k1.w;
        }
        __syncthreads();   // all warps done with this K buffer before overwrite
    }

    // Reduce + softmax (per warp)
#pragma unroll
    for (int w = 0; w < WW; w++) {
#pragma unroll
        for (int o = 16; o; o >>= 1) p[w] += __shfl_xor_sync(0xffffffffu, p[w], o);
    }
    if (lane == 0) {
        float mx = -1e30f;
#pragma unroll
        for (int w = 0; w < WW; w++) {
            int tt = t + w - HALF;
            p[w] = (tt >= 0 && tt < TT) ? p[w] * 0.03125f : -3.0e38f;
            mx = fmaxf(mx, p[w]);
        }
        float sum = 0.f;
#pragma unroll
        for (int w = 0; w < WW; w++) {
            float e = (p[w] > -1.0e38f) ? expf(p[w] - mx) : 0.f;
            swgt[warp][w] = e;
            sum += e;
        }
        const float inv = 1.f / sum;
#pragma unroll
        for (int w = 0; w < WW; w++) swgt[warp][w] *= inv;
    }
    __syncthreads();   // swgt visible
    float wgt[WW];
#pragma unroll
    for (int w = 0; w < WW; w++) wgt[w] = swgt[warp][w];

    // ---- Output pass over V chunks ----
    ATTN_ISSUE(sb[0], v, 0);
    for (int c = 0; c < NCH; c++) {
        cp_wait<0>();
        __syncthreads();
        if (c + 1 < NCH) ATTN_ISSUE(sb[(c + 1) & 1], v, c + 1);
        const float4* vb = (const float4*)bufp[c & 1];
        float4 a0 = make_float4(0.f, 0.f, 0.f, 0.f);
        float4 a1 = make_float4(0.f, 0.f, 0.f, 0.f);
#pragma unroll
        for (int w = 0; w < WW; w++) {
            int tt = t + w - HALF;
            if (tt < 0 || tt >= TT) continue;
            const float aw = wgt[w];
            float4 v0 = vb[(warp + w) * 64 + lane];
            float4 v1 = vb[(warp + w) * 64 + lane + 32];
            a0.x += aw * v0.x; a0.y += aw * v0.y; a0.z += aw * v0.z; a0.w += aw * v0.w;
            a1.x += aw * v1.x; a1.y += aw * v1.y; a1.z += aw * v1.z; a1.w += aw * v1.w;
        }
        store_h(ch, btrow + c * CHW + (size_t)lane * 4, a0);
        store_h(ch, btrow + c * CHW + (size_t)(lane + 32) * 4, a1);
        __syncthreads();   // all warps done with this V buffer before overwrite
    }
}

// ---------------------------------------------------------------------------
// Launch (5 launches; 2 and 4 are the GEMMs)
// ---------------------------------------------------------------------------
extern "C" void kernel_launch(void* const* d_in, const int* in_sizes, int n_in,
                              void* d_out, int out_size)
{
    const float* x  = (const float*)d_in[0];
    const float* Wq = (const float*)d_in[1];
    const float* bq = (const float*)d_in[2];
    const float* Wk = (const float*)d_in[3];
    const float* bk = (const float*)d_in[4];
    const float* Wv = (const float*)d_in[5];
    const float* bv = (const float*)d_in[6];
    const float* Wo = (const float*)d_in[7];
    const float* bo = (const float*)d_in[8];

    float *q, *k, *v;
    __half *x16, *c16, *w16;
    cudaGetSymbolAddress((void**)&q,   g_q);
    cudaGetSymbolAddress((void**)&k,   g_k);
    cudaGetSymbolAddress((void**)&v,   g_v);
    cudaGetSymbolAddress((void**)&x16, g_x16);
    cudaGetSymbolAddress((void**)&c16, g_c16);
    cudaGetSymbolAddress((void**)&w16, g_w16);

    cudaFuncSetAttribute(gemm_f16,   cudaFuncAttributeMaxDynamicSharedMemorySize, GEMM_SMEM);
    cudaFuncSetAttribute(local_attn, cudaFuncAttributeMaxDynamicSharedMemorySize, ATTN_SMEM);

    const int nx4 = MM * CC / 4;
    const int nw4 = CC * CC / 4;
    const size_t WSZ = (size_t)CC * CC;

    // 0: convert x -> fp16
    conv_f16<<<dim3(nx4 / 256, 1), 256>>>(x, x, x, x, x16, nx4);
    // 1: convert Wq|Wk|Wv|Wo -> fp16 segments 0..3
    conv_f16<<<dim3(nw4 / 256, 4), 256>>>(Wq, Wk, Wv, Wo, w16, nw4);
    // 2: fused QKV GEMM (persistent, 3072 tiles, nblk=48)
    gemm_f16<<<GRID_PERSIST, 256, GEMM_SMEM>>>(x16, w16,
                                               bq, bk, bv, q, k, v,
                                               (MM / BM) * 48, 48);
    // 3: chunked attention (writes ctx fp16)
    local_attn<<<dim3(TT / GG, BB), 256, ATTN_SMEM>>>(q, k, v, c16);
    // 4: output projection (persistent, 1024 tiles, nblk=16)
    gemm_f16<<<GRID_PERSIST, 256, GEMM_SMEM>>>(c16, w16 + 3 * WSZ,
                                               bo, bo, bo,
                                               (float*)d_out, (float*)d_out, (float*)d_out,
                                               (MM / BM) * 16, 16);
}

// round 17
// speedup vs baseline: 1.0826x; 1.0826x over previous
#include <cuda_runtime.h>
#include <cuda_bf16.h>
#include <cuda_fp16.h>
#include <math.h>
#include <cstdint>

// Problem constants (LocalAttention: B=4, T=2048, C=1024, WIN=16)
#define BB   4
#define TT   2048
#define CC   1024
#define HALF 8
#define WW   17
#define MM   8192

// GEMM tiling: CTA tile 128x64, warp tile 32x32, 8 warps (4M x 2N)
// BK=64 per stage (two 32-wide sub-tiles), 4 stages, 2 CTAs/SM.  (R14 config)
#define BM 128
#define BN 64
#define BKK 64                    // fp16 K elems per stage
#define NIT (CC / BKK)            // 16 k-iterations
#define ATILE_B 8192              // 128 rows x 32 f16 x 2B (one sub-tile)
#define BTILE_B 4096              // 64 rows x 32 f16 x 2B  (one sub-tile)
#define QSTAGE_B (2 * ATILE_B + 2 * BTILE_B)  // 24576
#define GEMM_SMEM (4 * QSTAGE_B)  // 98304
#define GRID_PERSIST 296          // 2 CTAs per SM

// Attention: block = 8 t-positions, C chunked into 4x256, double buffer
#define GG   8
#define CHW  256
#define NCH  4
#define WROWS 24
#define ATTN_SMEM (2 * WROWS * CHW * 4)   // 49152

// Conversion sizes (compile-time powers of two)
#define NX4 (MM * CC / 4)         // 2097152 = 1<<21
#define NW4 (CC * CC / 4)         // 262144  = 1<<18

// ---------------------------------------------------------------------------
// Scratch (device globals: allocation-free rule)
// ---------------------------------------------------------------------------
__device__ float g_q[MM * CC];
__device__ float g_k[MM * CC];
__device__ float g_v[MM * CC];
__device__ __half g_x16[MM * CC];
__device__ __half g_c16[MM * CC];
__device__ __half g_w16[4 * CC * CC];   // Wq, Wk, Wv, Wo (single fp16)

// ---------------------------------------------------------------------------
// PTX helpers (sm_80+ base-target instructions only)
// ---------------------------------------------------------------------------
__device__ __forceinline__ uint32_t smem_u32(const void* p) {
    uint32_t a;
    asm("{ .reg .u64 t; cvta.to.shared.u64 t, %1; cvt.u32.u64 %0, t; }" : "=r"(a) : "l"(p));
    return a;
}
__device__ __forceinline__ void cp_async16(uint32_t dst, const void* src) {
    asm volatile("cp.async.cg.shared.global [%0], [%1], 16;" :: "r"(dst), "l"(src));
}
__device__ __forceinline__ void cp_commit() { asm volatile("cp.async.commit_group;"); }
template <int N>
__device__ __forceinline__ void cp_wait() { asm volatile("cp.async.wait_group %0;" :: "n"(N)); }

__device__ __forceinline__ void ldsm_x4(uint32_t& r0, uint32_t& r1, uint32_t& r2, uint32_t& r3,
                                        uint32_t addr) {
    asm volatile("ldmatrix.sync.aligned.m8n8.x4.shared.b16 {%0,%1,%2,%3}, [%4];"
                 : "=r"(r0), "=r"(r1), "=r"(r2), "=r"(r3) : "r"(addr));
}
__device__ __forceinline__ void mma_f16(float* d, const uint32_t* a, uint32_t b0, uint32_t b1) {
    asm volatile(
        "mma.sync.aligned.m16n8k16.row.col.f32.f16.f16.f32 "
        "{%0,%1,%2,%3}, {%4,%5,%6,%7}, {%8,%9}, {%0,%1,%2,%3};"
        : "+f"(d[0]), "+f"(d[1]), "+f"(d[2]), "+f"(d[3])
        : "r"(a[0]), "r"(a[1]), "r"(a[2]), "r"(a[3]), "r"(b0), "r"(b1));
}

// Swizzle on 64B logical rows (conflict-free ldmatrix + STS16)
#define SWZ(off) ((off) ^ (((off) >> 3) & 0x70))

__device__ __forceinline__ uint32_t ldsm_addr(uint32_t tile_base, int row0, int chunk0, int lane) {
    int row   = row0 + (lane & 15);
    int chunk = chunk0 + (lane >> 4);
    uint32_t off = (uint32_t)row * 64 + (uint32_t)chunk * 16;
    return tile_base + SWZ(off);
}

// ---------------------------------------------------------------------------
// Fused fp32 -> fp16 conversion: x (NX4 quads) then Wq|Wk|Wv|Wo (NW4 each).
// ---------------------------------------------------------------------------
__global__ __launch_bounds__(256)
void conv_all(const float* __restrict__ x,
              const float* __restrict__ w0, const float* __restrict__ w1,
              const float* __restrict__ w2, const float* __restrict__ w3,
              __half* __restrict__ x16, __half* __restrict__ w16)
{
    const int i = blockIdx.x * 256 + threadIdx.x;
    const float* src;
    __half* dst;
    int idx;
    if (i < NX4) {
        src = x; dst = x16; idx = i;
    } else {
        const int j = i - NX4;
        const int seg = j >> 18;                 // NW4 = 1<<18
        const float* ws[4] = {w0, w1, w2, w3};
        src = ws[seg];
        dst = w16;
        idx = j;                                 // contiguous across w16 segments
        src = ws[seg] - ((size_t)seg << 18) * 4; // rebase so src[idx quads] hits seg offset
    }
    // For weight segments: idx spans [seg*NW4, (seg+1)*NW4); src rebased accordingly.
    float4 v = ((const float4*)src)[idx];
    __half h[4] = {__float2half(v.x), __float2half(v.y), __float2half(v.z), __float2half(v.w)};
    ((ushort4*)dst)[idx] =
        make_ushort4(*(unsigned short*)&h[0], *(unsigned short*)&h[1],
                     *(unsigned short*)&h[2], *(unsigned short*)&h[3]);
}

// ---------------------------------------------------------------------------
// Persistent fp16 NT GEMM, 128x64 CTA tile, BK=64, 4 stages, 2 CTAs/SM.
// out[m,n] = sum_k A[m,k]*W[n,k] + bias[n]
// nblk = weight 64-col blocks (48 fused QKV, 16 Wo); which = nb>>4.
// Next-tile prologue is issued BEFORE the epilogue: with 4 stages the final
// unsynced consumer reads stage 3 while the prologue writes stages 0-2, whose
// readers (it=12..14) are ordered by the it=13..15 top-of-loop barriers.
// ---------------------------------------------------------------------------
__global__ __launch_bounds__(256, 2)
void gemm_f16(const __half* __restrict__ Ah, const __half* __restrict__ Wh,
              const float* __restrict__ b0, const float* __restrict__ b1,
              const float* __restrict__ b2,
              float* __restrict__ o0, float* __restrict__ o1, float* __restrict__ o2,
              int ntiles, int nblk)
{
    extern __shared__ char sm[];
    const uint32_t sbase = smem_u32(sm);
    const int tid   = threadIdx.x;
    const int lane  = tid & 31;
    const int warp  = tid >> 5;
    const int warpM = warp >> 1;
    const int warpN = warp & 1;

    const int larow = tid >> 1;
    const int lac0  = (tid & 1) * 2;
    uint32_t daphys[2];
#pragma unroll
    for (int i = 0; i < 2; i++) {
        uint32_t off = (uint32_t)larow * 64 + (uint32_t)(lac0 + i) * 16;
        daphys[i] = SWZ(off);
    }
    const int lbrow = tid >> 2;
    const int lbc   = tid & 3;
    const uint32_t dbphys = SWZ((uint32_t)lbrow * 64 + (uint32_t)lbc * 16);

    int tile = (int)blockIdx.x;
    if (tile >= ntiles) return;
    int mb = tile / nblk;
    int nb = tile - mb * nblk;
    const __half* gA = Ah + (size_t)(mb * BM + larow) * CC;
    const __half* gW = Wh + (size_t)(nb * BN + lbrow) * CC;

// One stage = K range [kc, kc+64): two 32-wide sub-tiles for A and for W.
#define ISSUE_STAGE(s, kc) do { \
    uint32_t stg_ = sbase + (uint32_t)(s) * QSTAGE_B; \
    _Pragma("unroll") \
    for (int sub_ = 0; sub_ < 2; sub_++) { \
        _Pragma("unroll") \
        for (int i_ = 0; i_ < 2; i_++) { \
            cp_async16(stg_ + sub_ * ATILE_B + daphys[i_], \
                       gA + (kc) + sub_ * 32 + (lac0 + i_) * 8); \
        } \
        cp_async16(stg_ + 2 * ATILE_B + sub_ * BTILE_B + dbphys, \
                   gW + (kc) + sub_ * 32 + lbc * 8); \
    } \
    cp_commit(); \
} while (0)

    ISSUE_STAGE(0, 0);
    ISSUE_STAGE(1, 64);
    ISSUE_STAGE(2, 128);

    for (;;) {
        float acc[2][4][4];
#pragma unroll
        for (int mt = 0; mt < 2; mt++)
#pragma unroll
            for (int nt = 0; nt < 4; nt++)
#pragma unroll
                for (int r = 0; r < 4; r++) acc[mt][nt][r] = 0.f;

        for (int it = 0; it < NIT; it++) {
            cp_wait<2>();
            __syncthreads();
            if (it + 3 < NIT) { ISSUE_STAGE((it + 3) & 3, (it + 3) * BKK); }
            else              { cp_commit(); }   // keep group numbering advancing

            const uint32_t stg = sbase + (uint32_t)(it & 3) * QSTAGE_B;
#pragma unroll
            for (int g = 0; g < 4; g++) {        // four k16 steps per stage
                const int tsel = g >> 1;         // sub-tile
                const int ch0  = (g & 1) * 2;    // 16B-chunk within sub-tile
                uint32_t afr[2][4];              // [mt][reg]
#pragma unroll
                for (int mt = 0; mt < 2; mt++) {
                    uint32_t ad = ldsm_addr(stg + tsel * ATILE_B,
                                            warpM * 32 + mt * 16, ch0, lane);
                    ldsm_x4(afr[mt][0], afr[mt][1], afr[mt][2], afr[mt][3], ad);
                }
                uint32_t bfr[2][4];              // [gp][reg]
#pragma unroll
                for (int gp = 0; gp < 2; gp++) {
                    uint32_t ad = ldsm_addr(stg + 2 * ATILE_B + tsel * BTILE_B,
                                            warpN * 32 + gp * 16, ch0, lane);
                    ldsm_x4(bfr[gp][0], bfr[gp][1], bfr[gp][2], bfr[gp][3], ad);
                }
#pragma unroll
                for (int mt = 0; mt < 2; mt++)
#pragma unroll
                    for (int gp = 0; gp < 2; gp++) {
                        mma_f16(acc[mt][gp * 2 + 0], afr[mt], bfr[gp][0], bfr[gp][2]);
                        mma_f16(acc[mt][gp * 2 + 1], afr[mt], bfr[gp][1], bfr[gp][3]);
                    }
            }
        }

        // Current-tile epilogue coordinates (captured before advancing).
        const int ebm   = mb * BM;
        const int which = nb >> 4;
        const int col0  = (nb & 15) * BN;
        const float* bias = (which == 0) ? b0 : ((which == 1) ? b1 : b2);
        float* Cout       = (which == 0) ? o0 : ((which == 1) ? o1 : o2);

        // Prefetch next tile's first 3 stages before the epilogue (see header).
        const int ntile = tile + (int)gridDim.x;
        const bool more = ntile < ntiles;
        if (more) {
            tile = ntile;
            mb = tile / nblk;
            nb = tile - mb * nblk;
            gA = Ah + (size_t)(mb * BM + larow) * CC;
            gW = Wh + (size_t)(nb * BN + lbrow) * CC;
            ISSUE_STAGE(0, 0);
            ISSUE_STAGE(1, 64);
            ISSUE_STAGE(2, 128);
        }

        // Epilogue: bias + fp32 store
#pragma unroll
        for (int mt = 0; mt < 2; mt++) {
            const int row0 = ebm + warpM * 32 + mt * 16 + (lane >> 2);
#pragma unroll
            for (int nt = 0; nt < 4; nt++) {
                const int col = col0 + warpN * 32 + nt * 8 + (lane & 3) * 2;
                const float c0 = bias[col], c1 = bias[col + 1];
                float2 v0 = make_float2(acc[mt][nt][0] + c0, acc[mt][nt][1] + c1);
                float2 v1 = make_float2(acc[mt][nt][2] + c0, acc[mt][nt][3] + c1);
                *(float2*)(Cout + (size_t)row0 * CC + col)       = v0;
                *(float2*)(Cout + (size_t)(row0 + 8) * CC + col) = v1;
            }
        }
        if (!more) break;
    }
#undef ISSUE_STAGE
}

// ---------------------------------------------------------------------------
// Chunked smem local attention (R14 version): block = 8 t (1 warp each),
// C in 4x256 chunks, 2x24KB double-buffered window via cp.async.
// Buffer reuse is barrier-ordered: the issue for chunk c+2 (into buf c&1)
// occurs after the top-of-iteration barrier at c+1, which all warps reach
// only after finishing their compute on buf c.
// Writes ctx as single fp16.
// ---------------------------------------------------------------------------
__device__ __forceinline__ void store_h(__half* ch, size_t off, float4 a) {
    float f[4] = {a.x, a.y, a.z, a.w};
    unsigned short h[4];
#pragma unroll
    for (int c = 0; c < 4; c++) {
        __half hb = __float2half(f[c]);
        h[c] = *(unsigned short*)&hb;
    }
    *(ushort4*)(ch + off) = make_ushort4(h[0], h[1], h[2], h[3]);
}

#define ATTN_ISSUE(dstu32, srcp, c) do { \
    _Pragma("unroll") \
    for (int i_ = 0; i_ < 6; i_++) { \
        int idx_ = i_ * 256 + tid; \
        int r_ = idx_ >> 6, f4_ = idx_ & 63; \
        int trow_ = t0 - HALF + r_; \
        if (trow_ >= 0 && trow_ < TT) \
            cp_async16((dstu32) + ((uint32_t)r_ * CHW + f4_ * 4) * 4, \
                       (srcp) + base + (size_t)trow_ * CC + (c) * CHW + f4_ * 4); \
    } \
    cp_commit(); \
} while (0)

__global__ __launch_bounds__(256)
void local_attn(const float* __restrict__ q, const float* __restrict__ k,
                const float* __restrict__ v, __half* __restrict__ ch)
{
    extern __shared__ float sh[];
    float* bufp[2] = { sh, sh + WROWS * CHW };
    __shared__ float swgt[GG][WW];

    const int b    = blockIdx.y;
    const int t0   = blockIdx.x * GG;
    const int tid  = threadIdx.x;
    const int warp = tid >> 5;
    const int lane = tid & 31;
    const uint32_t sb[2] = { smem_u32(bufp[0]), smem_u32(bufp[1]) };
    const size_t base = (size_t)b * TT * CC;

    const int t = t0 + warp;
    const size_t btrow = base + (size_t)t * CC;

    float p[WW];
#pragma unroll
    for (int w = 0; w < WW; w++) p[w] = 0.f;

    // ---- Score pass over K chunks ----
    ATTN_ISSUE(sb[0], k, 0);
    for (int c = 0; c < NCH; c++) {
        cp_wait<0>();
        __syncthreads();
        if (c + 1 < NCH) ATTN_ISSUE(sb[(c + 1) & 1], k, c + 1);
        const float4* kb = (const float4*)bufp[c & 1];
        const float4* qr = (const float4*)(q + btrow);
        float4 q0 = qr[c * 64 + lane];
        float4 q1 = qr[c * 64 + lane + 32];
#pragma unroll
        for (int w = 0; w < WW; w++) {
            int tt = t + w - HALF;
            if (tt < 0 || tt >= TT) continue;
            float4 k0 = kb[(warp + w) * 64 + lane];
            float4 k1 = kb[(warp + w) * 64 + lane + 32];
            p[w] += q0.x * k0.x + q0.y * k0.y + q0.z * k0.z + q0.w * k0.w
                  + q1.x * k1.x + q1.y * k1.y + q1.z * k1.z + q1.w * k1.w;
        }
    }

    // Reduce + softmax (per warp)
#pragma unroll
    for (int w = 0; w < WW; w++) {
#pragma unroll
        for (int o = 16; o; o >>= 1) p[w] += __shfl_xor_sync(0xffffffffu, p[w], o);
    }
    if (lane == 0) {
        float mx = -1e30f;
#pragma unroll
        for (int w = 0; w < WW; w++) {
            int tt = t + w - HALF;
            p[w] = (tt >= 0 && tt < TT) ? p[w] * 0.03125f : -3.0e38f;
            mx = fmaxf(mx, p[w]);
        }
        float sum = 0.f;
#pragma unroll
        for (int w = 0; w < WW; w++) {
            float e = (p[w] > -1.0e38f) ? expf(p[w] - mx) : 0.f;
            swgt[warp][w] = e;
            sum += e;
        }
        const float inv = 1.f / sum;
#pragma unroll
        for (int w = 0; w < WW; w++) swgt[warp][w] *= inv;
    }
    __syncthreads();   // swgt visible; all warps done with K buffers
    float wgt[WW];
#pragma unroll
    for (int w = 0; w < WW; w++) wgt[w] = swgt[warp][w];

    // ---- Output pass over V chunks ----
    ATTN_ISSUE(sb[0], v, 0);
    for (int c = 0; c < NCH; c++) {
        cp_wait<0>();
        __syncthreads();
        if (c + 1 < NCH) ATTN_ISSUE(sb[(c + 1) & 1], v, c + 1);
        const float4* vb = (const float4*)bufp[c & 1];
        float4 a0 = make_float4(0.f, 0.f, 0.f, 0.f);
        float4 a1 = make_float4(0.f, 0.f, 0.f, 0.f);
#pragma unroll
        for (int w = 0; w < WW; w++) {
            int tt = t + w - HALF;
            if (tt < 0 || tt >= TT) continue;
            const float aw = wgt[w];
            float4 v0 = vb[(warp + w) * 64 + lane];
            float4 v1 = vb[(warp + w) * 64 + lane + 32];
            a0.x += aw * v0.x; a0.y += aw * v0.y; a0.z += aw * v0.z; a0.w += aw * v0.w;
            a1.x += aw * v1.x; a1.y += aw * v1.y; a1.z += aw * v1.z; a1.w += aw * v1.w;
        }
        store_h(ch, btrow + c * CHW + (size_t)lane * 4, a0);
        store_h(ch, btrow + c * CHW + (size_t)(lane + 32) * 4, a1);
    }
}

// ---------------------------------------------------------------------------
// Launch (4 launches; 1 and 3 are the GEMMs)
// ---------------------------------------------------------------------------
extern "C" void kernel_launch(void* const* d_in, const int* in_sizes, int n_in,
                              void* d_out, int out_size)
{
    const float* x  = (const float*)d_in[0];
    const float* Wq = (const float*)d_in[1];
    const float* bq = (const float*)d_in[2];
    const float* Wk = (const float*)d_in[3];
    const float* bk = (const float*)d_in[4];
    const float* Wv = (const float*)d_in[5];
    const float* bv = (const float*)d_in[6];
    const float* Wo = (const float*)d_in[7];
    const float* bo = (const float*)d_in[8];

    float *q, *k, *v;
    __half *x16, *c16, *w16;
    cudaGetSymbolAddress((void**)&q,   g_q);
    cudaGetSymbolAddress((void**)&k,   g_k);
    cudaGetSymbolAddress((void**)&v,   g_v);
    cudaGetSymbolAddress((void**)&x16, g_x16);
    cudaGetSymbolAddress((void**)&c16, g_c16);
    cudaGetSymbolAddress((void**)&w16, g_w16);

    cudaFuncSetAttribute(gemm_f16,   cudaFuncAttributeMaxDynamicSharedMemorySize, GEMM_SMEM);
    cudaFuncSetAttribute(local_attn, cudaFuncAttributeMaxDynamicSharedMemorySize, ATTN_SMEM);

    const size_t WSZ = (size_t)CC * CC;

    // 0: fused conversion of x + Wq|Wk|Wv|Wo -> fp16
    conv_all<<<(NX4 + 4 * NW4) / 256, 256>>>(x, Wq, Wk, Wv, Wo, x16, w16);
    // 1: fused QKV GEMM (persistent, 3072 tiles, nblk=48)
    gemm_f16<<<GRID_PERSIST, 256, GEMM_SMEM>>>(x16, w16,
                                               bq, bk, bv, q, k, v,
                                               (MM / BM) * 48, 48);
    // 2: chunked attention (writes ctx fp16)
    local_attn<<<dim3(TT / GG, BB), 256, ATTN_SMEM>>>(q, k, v, c16);
    // 3: output projection (persistent, 1024 tiles, nblk=16)
    gemm_f16<<<GRID_PERSIST, 256, GEMM_SMEM>>>(c16, w16 + 3 * WSZ,
                                               bo, bo, bo,
                                               (float*)d_out, (float*)d_out, (float*)d_out,
                                               (MM / BM) * 16, 16);
}